// round 9
// baseline (speedup 1.0000x reference)
#include <cuda_runtime.h>
#include <stdint.h>

#define N_TOKENS 131072
#define D_MODEL  512
#define PATHS    16
#define CAP      16384                 // 2 * N / P
#define D4       (D_MODEL / 4)         // 128 float4 per row
#define ROWS     (PATHS * CAP)         // 262144 output rows
#define N_ZW     (ROWS - N_TOKENS)     // 131072 dedicated zero warps

#define TPB      512                   // 16 warps
#define NWARP    16
#define NB_R     256                   // route blocks (bid < NB_R): 256*512 = N_TOKENS
#define GRID_G   (ROWS / NWARP)        // 16384 blocks, one output row per warp

// ---- scratch (no allocations allowed; zero-initialized at load) ----
__device__ int      g_cnt[PATHS];          // per-path kept count (clamped to CAP)
__device__ int      g_zbase[PATHS + 1];    // prefix of zero-row counts per path
__device__ int      g_dst[N_TOKENS];       // token -> output row, or -(zero-duty)-1
__device__ int      g_hist[PATHS * NB_R];  // per-(path, block) counts  [path][block]
__device__ unsigned g_arrive;              // route-internal barrier counter
__device__ unsigned g_done;                // route completion counter
__device__ unsigned g_flag;                // route->scatter release flag
__device__ unsigned g_exit;                // kernel exit counter (self-clean)

__device__ __forceinline__ unsigned vload(const unsigned* p) {
    return *(volatile const unsigned*)p;
}

__global__ __launch_bounds__(TPB, 3) void k_fused(const float* __restrict__ score,
                                                  const float4* __restrict__ in4,
                                                  float4* __restrict__ out4) {
    __shared__ int sh_cnt[NWARP][PATHS];
    __shared__ int sh_wexcl[NWARP][PATHS];
    __shared__ int sh_excl[PATHS];
    __shared__ int sh_tot[PATHS];
    __shared__ int sh_obase[PATHS];
    __shared__ int sh_run[NWARP][PATHS];
    __shared__ int sh_last;
    const int tid = threadIdx.x, w = tid >> 5, lane = tid & 31, bid = blockIdx.x;
    const int G = bid * NWARP + w;                     // global warp id = output duty

    // ================= ROUTE PHASE (blocks 0..NB_R-1 only) =================
    if (bid < NB_R) {
        const int tok = bid * TPB + tid;               // one token per thread

        if (lane < PATHS) sh_cnt[w][lane] = 0;
        __syncwarp();
        int best;
        {
            const float4* sc = (const float4*)(score + (size_t)tok * PATHS);
            float4 a = __ldcs(sc), b = __ldcs(sc + 1), c = __ldcs(sc + 2), d = __ldcs(sc + 3);
            float v[16] = {a.x,a.y,a.z,a.w, b.x,b.y,b.z,b.w,
                           c.x,c.y,c.z,c.w, d.x,d.y,d.z,d.w};
            best = 0; float bv = v[0];
            #pragma unroll
            for (int p = 1; p < 16; p++) if (v[p] > bv) { bv = v[p]; best = p; }  // first-max
            unsigned m = __match_any_sync(0xffffffffu, best);
            if ((__ffs(m) - 1) == lane) sh_cnt[w][best] += __popc(m);
        }
        __syncthreads();

        if (w == 0 && lane < PATHS) {                  // block scan + publish aggregate
            int run = 0;
            #pragma unroll
            for (int ww = 0; ww < NWARP; ww++) { int v = sh_cnt[ww][lane]; sh_wexcl[ww][lane] = run; run += v; }
            g_hist[lane * NB_R + bid] = run;           // [path][block]
            __threadfence();
        }
        __syncthreads();

        if (tid == 0) {                                // resident barrier over route blocks
            atomicAdd(&g_arrive, 1u);
            while (vload(&g_arrive) < (unsigned)NB_R) { }
        }
        __syncthreads();

        {                                              // bulk prefix: warp w owns path w
            int excl = 0, tot = 0;
            #pragma unroll
            for (int s = 0; s < NB_R / 32; s++) {
                const int j = s * 32 + lane;
                const int v = g_hist[w * NB_R + j];
                tot += v;
                if (j < bid) excl += v;
            }
            excl = __reduce_add_sync(0xffffffffu, excl);
            tot  = __reduce_add_sync(0xffffffffu, tot);
            if (lane == 0) { sh_excl[w] = excl; sh_tot[w] = tot; }
        }
        __syncthreads();

        // per-path overflow base (for dropped-token zero duties)
        if (w < 1 && lane < PATHS) {
            int ob = 0;
            #pragma unroll
            for (int q = 0; q < PATHS; q++) {
                int o = sh_tot[q] - CAP; o = o > 0 ? o : 0;
                if (q < lane) ob += o;
            }
            sh_obase[lane] = ob;
        }
        if (bid == 0) {                                // block 0 publishes cnt + zbase
            if (w == 1 && lane < PATHS) { int t = sh_tot[lane]; g_cnt[lane] = t < CAP ? t : CAP; }
            if (w == 2 && lane == 0) {
                int zb = 0;
                #pragma unroll
                for (int p = 0; p < PATHS; p++) {
                    g_zbase[p] = zb;
                    int c = sh_tot[p] < CAP ? sh_tot[p] : CAP;
                    zb += CAP - c;
                }
                g_zbase[PATHS] = zb;
            }
        }
        __syncthreads();

        // order-preserving rank -> token destination map
        if (lane < PATHS) sh_run[w][lane] = sh_excl[lane] + sh_wexcl[w][lane];
        __syncwarp();
        {
            unsigned m = __match_any_sync(0xffffffffu, best);
            const int rank = __popc(m & ((1u << lane) - 1u));
            const int pos = sh_run[w][best] + rank;
            g_dst[tok] = (pos < CAP) ? (best * CAP + pos)
                                     : (-(sh_obase[best] + (pos - CAP)) - 1);
        }

        __threadfence();
        __syncthreads();
        if (tid == 0) {
            if (atomicAdd(&g_done, 1u) == (unsigned)(NB_R - 1))
                atomicExch(&g_flag, 1u);
        }
    }

    // ================= SCATTER/ZERO PHASE (all blocks) =================
    const bool is_copy = (G < N_TOKENS);
    float4 v0 = make_float4(0.f,0.f,0.f,0.f);
    float4 v1 = v0, v2 = v0, v3 = v0;
    if (is_copy) {                                     // prefetch BEFORE the gate:
        const float4* src = in4 + (size_t)G * D4 + lane;   // source = own token row,
        v0 = src[0];                                       // independent of routing
        v1 = src[32];
        v2 = src[64];
        v3 = src[96];
    }

    if (tid == 0) { while (vload(&g_flag) == 0u) { } }
    __syncthreads();
    __threadfence();

    int row;
    int k = -1;                                        // zero-duty index, -1 = copy
    if (is_copy) {
        const int d = g_dst[G];
        if (d >= 0) row = d;
        else        k = N_ZW + (-d - 1);               // dropped token -> extra zero duty
    } else {
        k = G - N_TOKENS;
    }
    if (k >= 0) {
        v0 = v1 = v2 = v3 = make_float4(0.f,0.f,0.f,0.f);
        int zb = (lane <= PATHS) ? g_zbase[lane] : 0x7fffffff;
        int zbn = __shfl_down_sync(0xffffffffu, zb, 1);
        if (lane >= PATHS) zbn = 0x7fffffff;
        bool hit = (lane < PATHS) && (k >= zb) && (k < zbn);
        const int p = __ffs(__ballot_sync(0xffffffffu, hit)) - 1;
        const int base = __shfl_sync(0xffffffffu, zb, p);
        row = p * CAP + g_cnt[p] + (k - base);
    }
    float4* dst = out4 + (size_t)row * D4 + lane;
    dst[0]  = v0;
    dst[32] = v1;
    dst[64] = v2;
    dst[96] = v3;

    // ================= SELF-CLEAN (deterministic graph replay) =================
    __syncthreads();
    if (tid == 0) sh_last = (atomicAdd(&g_exit, 1u) == (unsigned)(GRID_G - 1));
    __syncthreads();
    if (sh_last && tid == 0) { g_arrive = 0; g_done = 0; g_flag = 0; g_exit = 0; }
}

extern "C" void kernel_launch(void* const* d_in, const int* in_sizes, int n_in,
                              void* d_out, int out_size) {
    const float* inputs = (const float*)d_in[0];
    const float* score  = (const float*)d_in[1];
    if (in_sizes[0] == N_TOKENS * PATHS) {   // defensive: identify by element count
        inputs = (const float*)d_in[1];
        score  = (const float*)d_in[0];
    }
    k_fused<<<GRID_G, TPB>>>(score, (const float4*)inputs, (float4*)d_out);
}